// round 9
// baseline (speedup 1.0000x reference)
#include <cuda_runtime.h>

// Per-CTA partial sums + completion counter. 16384/2 = 8192 CTAs for this problem.
__device__ float g_block[65536];
__device__ unsigned int g_count = 0;

__device__ __forceinline__ float warp_sum(float v) {
    #pragma unroll
    for (int off = 16; off > 0; off >>= 1)
        v += __shfl_down_sync(0xFFFFFFFFu, v, off);
    return v;
}

// 4 warps per i (each warp owns one quarter of the D dimension), 2 i per CTA.
// Rationale (R8 post-mortem): the old 1-warp-per-i layout serialized 4 memory
// round-trips per warp (loads->FMA->loads->FMA...). Here each warp has ONE
// front-batched 12-load round-trip, and 4x as many warps overlap each other.
// Epilogue: per-warp partials combine in smem; CTA writes g_block[bid]; the
// last CTA reduces all partials in fixed order (deterministic). Completion
// via acq_rel atomic (NOT __threadfence -> no CCTL.IVALL L1 flush, -5us R5/R7).
// Anchors via __ldcs (streaming, -33MB DRAM measured R7); gathers default .ca.
__global__ void __launch_bounds__(256)
triplet_fused(const float* __restrict__ feats,
              const float* __restrict__ label,
              const int*   __restrict__ idx1,
              const int*   __restrict__ idx2,
              float* __restrict__ out,
              int B, int D) {
    const int lane = threadIdx.x & 31;
    const int wid  = threadIdx.x >> 5;   // 0..7
    const int iq   = wid & 3;            // quarter of D owned by this warp
    const int il   = wid >> 2;           // local i index (0..1)
    const int i    = blockIdx.x * 2 + il;

    __shared__ float sh1[8], sh2[8], wloss[2];
    __shared__ bool  isLast;

    float s1 = 0.f, s2 = 0.f;
    int a = 0, b = 0;

    if (i < B) {
        // _fix_indices replication (broadcast loads; recomputed by all 4 warps of i)
        const int r1 = idx1[i];
        const int r2 = idx2[i];
        a = (i + 1 + (r1 % (B - 1))) % B;
        b = (i + 1 + (r2 % (B - 1))) % B;
        if (b == a) b = (i + 1 + ((r2 + 1) % (B - 1))) % B;

        const float4* __restrict__ A  = (const float4*)(feats + (size_t)i * D);
        const float4* __restrict__ T1 = (const float4*)(feats + (size_t)a * D);
        const float4* __restrict__ T2 = (const float4*)(feats + (size_t)b * D);

        const int n4 = D >> 2;   // 512 for D=2048

        if (n4 == 512) {
            // One 12-deep front-batched load set; single memory round-trip.
            const int base = lane + iq * 128;
            float4 av[4], v1[4], v2[4];
            #pragma unroll
            for (int u = 0; u < 4; ++u) av[u] = __ldcs(&A[base + u * 32]);
            #pragma unroll
            for (int u = 0; u < 4; ++u) v1[u] = T1[base + u * 32];
            #pragma unroll
            for (int u = 0; u < 4; ++u) v2[u] = T2[base + u * 32];
            #pragma unroll
            for (int u = 0; u < 4; ++u) {
                float d;
                d = av[u].x - v1[u].x; s1 = fmaf(d, d, s1);
                d = av[u].y - v1[u].y; s1 = fmaf(d, d, s1);
                d = av[u].z - v1[u].z; s1 = fmaf(d, d, s1);
                d = av[u].w - v1[u].w; s1 = fmaf(d, d, s1);
                d = av[u].x - v2[u].x; s2 = fmaf(d, d, s2);
                d = av[u].y - v2[u].y; s2 = fmaf(d, d, s2);
                d = av[u].z - v2[u].z; s2 = fmaf(d, d, s2);
                d = av[u].w - v2[u].w; s2 = fmaf(d, d, s2);
            }
        } else {
            // Generic path: warp iq covers j = lane + iq*32 stepping by 128.
            for (int j = lane + iq * 32; j < n4; j += 128) {
                float4 av = A[j];
                float4 v1 = T1[j];
                float4 v2 = T2[j];
                float d;
                d = av.x - v1.x; s1 = fmaf(d, d, s1);
                d = av.y - v1.y; s1 = fmaf(d, d, s1);
                d = av.z - v1.z; s1 = fmaf(d, d, s1);
                d = av.w - v1.w; s1 = fmaf(d, d, s1);
                d = av.x - v2.x; s2 = fmaf(d, d, s2);
                d = av.y - v2.y; s2 = fmaf(d, d, s2);
                d = av.z - v2.z; s2 = fmaf(d, d, s2);
                d = av.w - v2.w; s2 = fmaf(d, d, s2);
            }
        }

        s1 = warp_sum(s1);
        s2 = warp_sum(s2);
    }

    if (lane == 0) { sh1[wid] = s1; sh2[wid] = s2; }
    __syncthreads();

    // One leader thread per i (lane 0 of quarter-0 warp) finishes the loss.
    if ((threadIdx.x & 127) == 0) {
        float loss = 0.f;
        if (i < B) {
            const int wb = il * 4;
            float t1s = (sh1[wb] + sh1[wb + 1]) + (sh1[wb + 2] + sh1[wb + 3]);
            float t2s = (sh2[wb] + sh2[wb + 1]) + (sh2[wb + 2] + sh2[wb + 3]);

            const float mu    = (float)136.72353790613718;
            const float sigma = (float)62.34640414043511;

            float li_raw = label[i];
            float la = label[a]; if (a < i) la = (la - mu) / sigma;  // normalized by earlier step
            float lb = label[b]; if (b < i) lb = (lb - mu) / sigma;

            float ld1 = fabsf(li_raw - la);
            float ld2 = fabsf(li_raw - lb);
            bool cond = (ld1 >= ld2);

            float dp = cond ? t2s : t1s;   // anchor->near squared distance
            float dn = cond ? t1s : t2s;   // anchor->far  squared distance
            float near_l = cond ? lb : la;
            float far_l  = cond ? la : lb;

            float li = (li_raw - mu) / sigma;
            float nl = (near_l - mu) / sigma;  // may be double-normalized — matches reference
            float fl = (far_l  - mu) / sigma;

            float alpha = (li - fl) * (li - fl) - (li - nl) * (li - nl);
            float l = dp - dn + 0.5f * alpha;
            loss = l > 0.f ? l : 0.f;
        }
        wloss[il] = loss;
    }
    __syncthreads();

    if (threadIdx.x == 0) {
        float s = wloss[0] + wloss[1];
        __stcg(&g_block[blockIdx.x], s);   // bypass L1, publish to L2

        // acq_rel atomic: releases the __stcg above, acquires for the
        // __ldcg reads below. No CCTL.IVALL (unlike __threadfence).
        unsigned int old;
        asm volatile("atom.acq_rel.gpu.global.add.u32 %0, [%1], %2;"
                     : "=r"(old) : "l"(&g_count), "r"(1u) : "memory");
        isLast = (old == (unsigned int)gridDim.x - 1u);
    }
    __syncthreads();

    if (isLast) {
        // Partials are L2-hot (just written via __stcg). Fixed order.
        const int nb = gridDim.x;
        float s = 0.f;
        if ((nb & 3) == 0) {
            const float4* __restrict__ gb = (const float4*)g_block;
            const int nb4 = nb >> 2;       // 2048 for 8192 CTAs
            for (int j = (int)threadIdx.x; j < nb4; j += 256) {
                float4 v;
                v.x = __ldcg(&((const float*)gb)[4 * j + 0]);
                v.y = __ldcg(&((const float*)gb)[4 * j + 1]);
                v.z = __ldcg(&((const float*)gb)[4 * j + 2]);
                v.w = __ldcg(&((const float*)gb)[4 * j + 3]);
                s += (v.x + v.y) + (v.z + v.w);
            }
        } else {
            for (int j = (int)threadIdx.x; j < nb; j += 256)
                s += __ldcg(&g_block[j]);
        }

        __shared__ float sh[8];
        s = warp_sum(s);
        if (lane == 0) sh[wid] = s;
        __syncthreads();
        if (threadIdx.x == 0) {
            float t = 0.f;
            #pragma unroll
            for (int w = 0; w < 8; w++) t += sh[w];
            out[0] = t;
            g_count = 0;  // reset for next graph replay
        }
    }
}

extern "C" void kernel_launch(void* const* d_in, const int* in_sizes, int n_in,
                              void* d_out, int out_size) {
    const float* feats = (const float*)d_in[0];
    const float* label = (const float*)d_in[1];
    const int*   idx1  = (const int*)d_in[2];
    const int*   idx2  = (const int*)d_in[3];

    const int B = in_sizes[1];
    const int D = in_sizes[0] / B;
    const int nblocks = (B + 1) / 2;   // 2 i per CTA

    triplet_fused<<<nblocks, 256>>>(feats, label, idx1, idx2, (float*)d_out, B, D);
}

// round 11
// speedup vs baseline: 1.1928x; 1.1928x over previous
#include <cuda_runtime.h>

// Per-CTA partial sums + completion counter. 16384/8 = 2048 CTAs here.
__device__ float g_block[65536];
__device__ unsigned int g_count = 0;

__device__ __forceinline__ float warp_sum(float v) {
    #pragma unroll
    for (int off = 16; off > 0; off >>= 1)
        v += __shfl_down_sync(0xFFFFFFFFu, v, off);
    return v;
}

__device__ __forceinline__ void cp_async16(void* smem_dst, const void* gsrc) {
    unsigned s = (unsigned)__cvta_generic_to_shared(smem_dst);
    asm volatile("cp.async.cg.shared.global [%0], [%1], 16;" :: "r"(s), "l"(gsrc) : "memory");
}
__device__ __forceinline__ void cp_commit() {
    asm volatile("cp.async.commit_group;" ::: "memory");
}
__device__ __forceinline__ void cp_wait1() {
    asm volatile("cp.async.wait_group 1;" ::: "memory");
}

// Pipelined design (R9 post-mortem): register-resident gathers cap in-flight
// traffic at (regs/48)*occupancy; nothing saturates (DRAM<50%). cp.async into
// smem decouples load-issue from registers: gathers for i_{s+2} prefetched
// while computing i_s. Anchors are register-prefetched one stage ahead via
// __ldcs (streaming; R7 win). Index math + label loads done ONCE per CTA
// (R9 showed replicated %-division costs real ALU). Epilogue: __stcg +
// acq_rel atomic (no CCTL.IVALL; R5/R7 win), last CTA reduces, fixed order.
__global__ void __launch_bounds__(256)
triplet_fused(const float* __restrict__ feats,
              const float* __restrict__ label,
              const int*   __restrict__ idx1,
              const int*   __restrict__ idx2,
              float* __restrict__ out,
              int B, int D) {
    __shared__ float4 buf[2][1024];     // [stage][t1:512 | t2:512] = 32 KB
    __shared__ int    sa[8], sb[8];
    __shared__ float  slab_i[8], slab_a[8], slab_b[8];
    __shared__ float  sh1[8], sh2[8];
    __shared__ bool   isLast;

    const int tid  = threadIdx.x;
    const int lane = tid & 31;
    const int wid  = tid >> 5;
    const float mu    = (float)136.72353790613718;
    const float sigma = (float)62.34640414043511;

    float cta_loss = 0.f;

    if (D == 2048 && (B & 7) == 0 && (blockIdx.x + 1) * 8 <= B) {
        const int i0 = blockIdx.x * 8;

        // Per-CTA precompute: indices (one %-division per i, not per lane) + labels.
        if (tid < 8) {
            const int i = i0 + tid;
            const int r1 = idx1[i];
            const int r2 = idx2[i];
            int a = (i + 1 + (r1 % (B - 1))) % B;
            int b = (i + 1 + (r2 % (B - 1))) % B;
            if (b == a) b = (i + 1 + ((r2 + 1) % (B - 1))) % B;
            sa[tid] = a; sb[tid] = b;
            slab_i[tid] = label[i];
            slab_a[tid] = label[a];
            slab_b[tid] = label[b];
        }
        __syncthreads();

        // Prefetch gathers for i0, i1 into the two stages.
        {
            const float4* T1 = (const float4*)(feats + (size_t)sa[0] * 2048);
            const float4* T2 = (const float4*)(feats + (size_t)sb[0] * 2048);
            cp_async16(&buf[0][tid],        &T1[tid]);
            cp_async16(&buf[0][tid + 256],  &T1[tid + 256]);
            cp_async16(&buf[0][512 + tid],       &T2[tid]);
            cp_async16(&buf[0][512 + tid + 256], &T2[tid + 256]);
            cp_commit();
            const float4* U1 = (const float4*)(feats + (size_t)sa[1] * 2048);
            const float4* U2 = (const float4*)(feats + (size_t)sb[1] * 2048);
            cp_async16(&buf[1][tid],        &U1[tid]);
            cp_async16(&buf[1][tid + 256],  &U1[tid + 256]);
            cp_async16(&buf[1][512 + tid],       &U2[tid]);
            cp_async16(&buf[1][512 + tid + 256], &U2[tid + 256]);
            cp_commit();
        }

        // Anchor regs for i0.
        const float4* A0 = (const float4*)(feats + (size_t)i0 * 2048);
        float4 av0 = __ldcs(&A0[tid]);
        float4 av1 = __ldcs(&A0[tid + 256]);

        #pragma unroll 2
        for (int s = 0; s < 8; ++s) {
            cp_wait1();            // stage s%2 (gathers of i_s) complete
            __syncthreads();
            const int st = s & 1;

            // Issue next anchor load early (hidden behind this stage's work).
            float4 an0 = make_float4(0.f, 0.f, 0.f, 0.f), an1 = an0;
            if (s + 1 < 8) {
                const float4* An = (const float4*)(feats + (size_t)(i0 + s + 1) * 2048);
                an0 = __ldcs(&An[tid]);
                an1 = __ldcs(&An[tid + 256]);
            }

            const float4 v1a = buf[st][tid];
            const float4 v1b = buf[st][tid + 256];
            const float4 v2a = buf[st][512 + tid];
            const float4 v2b = buf[st][512 + tid + 256];

            float s1 = 0.f, s2 = 0.f, d;
            d = av0.x - v1a.x; s1 = fmaf(d, d, s1);
            d = av0.y - v1a.y; s1 = fmaf(d, d, s1);
            d = av0.z - v1a.z; s1 = fmaf(d, d, s1);
            d = av0.w - v1a.w; s1 = fmaf(d, d, s1);
            d = av1.x - v1b.x; s1 = fmaf(d, d, s1);
            d = av1.y - v1b.y; s1 = fmaf(d, d, s1);
            d = av1.z - v1b.z; s1 = fmaf(d, d, s1);
            d = av1.w - v1b.w; s1 = fmaf(d, d, s1);
            d = av0.x - v2a.x; s2 = fmaf(d, d, s2);
            d = av0.y - v2a.y; s2 = fmaf(d, d, s2);
            d = av0.z - v2a.z; s2 = fmaf(d, d, s2);
            d = av0.w - v2a.w; s2 = fmaf(d, d, s2);
            d = av1.x - v2b.x; s2 = fmaf(d, d, s2);
            d = av1.y - v2b.y; s2 = fmaf(d, d, s2);
            d = av1.z - v2b.z; s2 = fmaf(d, d, s2);
            d = av1.w - v2b.w; s2 = fmaf(d, d, s2);

            s1 = warp_sum(s1);
            s2 = warp_sum(s2);
            if (lane == 0) { sh1[wid] = s1; sh2[wid] = s2; }
            __syncthreads();   // stage st free; sh readable by leader

            if (tid == 0) {
                float t1s = ((sh1[0] + sh1[1]) + (sh1[2] + sh1[3]))
                          + ((sh1[4] + sh1[5]) + (sh1[6] + sh1[7]));
                float t2s = ((sh2[0] + sh2[1]) + (sh2[2] + sh2[3]))
                          + ((sh2[4] + sh2[5]) + (sh2[6] + sh2[7]));

                const int i = i0 + s;
                const int a = sa[s], b = sb[s];
                float li_raw = slab_i[s];
                float la = slab_a[s]; if (a < i) la = (la - mu) / sigma;  // earlier-step normalize
                float lb = slab_b[s]; if (b < i) lb = (lb - mu) / sigma;

                float ld1 = fabsf(li_raw - la);
                float ld2 = fabsf(li_raw - lb);
                bool cond = (ld1 >= ld2);

                float dp = cond ? t2s : t1s;
                float dn = cond ? t1s : t2s;
                float near_l = cond ? lb : la;
                float far_l  = cond ? la : lb;

                float li = (li_raw - mu) / sigma;
                float nl = (near_l - mu) / sigma;  // may be double-normalized — matches reference
                float fl = (far_l  - mu) / sigma;

                float alpha = (li - fl) * (li - fl) - (li - nl) * (li - nl);
                float l = dp - dn + 0.5f * alpha;
                cta_loss += (l > 0.f ? l : 0.f);
            }

            // Prefetch gathers for i_{s+2} into the stage just freed.
            if (s + 2 < 8) {
                const float4* T1 = (const float4*)(feats + (size_t)sa[s + 2] * 2048);
                const float4* T2 = (const float4*)(feats + (size_t)sb[s + 2] * 2048);
                cp_async16(&buf[st][tid],        &T1[tid]);
                cp_async16(&buf[st][tid + 256],  &T1[tid + 256]);
                cp_async16(&buf[st][512 + tid],       &T2[tid]);
                cp_async16(&buf[st][512 + tid + 256], &T2[tid + 256]);
            }
            cp_commit();   // commit every iter (possibly empty) to keep wait_group<1> counting exact

            av0 = an0; av1 = an1;
        }
    } else {
        // Generic fallback: one warp per i (R7 structure).
        __shared__ float wl[8];
        const int i = blockIdx.x * 8 + wid;
        float loss = 0.f;
        if (i < B) {
            const int r1 = idx1[i];
            const int r2 = idx2[i];
            int a = (i + 1 + (r1 % (B - 1))) % B;
            int b = (i + 1 + (r2 % (B - 1))) % B;
            if (b == a) b = (i + 1 + ((r2 + 1) % (B - 1))) % B;

            const float4* A  = (const float4*)(feats + (size_t)i * D);
            const float4* T1 = (const float4*)(feats + (size_t)a * D);
            const float4* T2 = (const float4*)(feats + (size_t)b * D);
            const int n4 = D >> 2;
            float s1 = 0.f, s2 = 0.f;
            for (int j = lane; j < n4; j += 32) {
                float4 av = A[j], v1 = T1[j], v2 = T2[j];
                float d;
                d = av.x - v1.x; s1 = fmaf(d, d, s1);
                d = av.y - v1.y; s1 = fmaf(d, d, s1);
                d = av.z - v1.z; s1 = fmaf(d, d, s1);
                d = av.w - v1.w; s1 = fmaf(d, d, s1);
                d = av.x - v2.x; s2 = fmaf(d, d, s2);
                d = av.y - v2.y; s2 = fmaf(d, d, s2);
                d = av.z - v2.z; s2 = fmaf(d, d, s2);
                d = av.w - v2.w; s2 = fmaf(d, d, s2);
            }
            s1 = warp_sum(s1);
            s2 = warp_sum(s2);
            if (lane == 0) {
                float li_raw = label[i];
                float la = label[a]; if (a < i) la = (la - mu) / sigma;
                float lb = label[b]; if (b < i) lb = (lb - mu) / sigma;
                float ld1 = fabsf(li_raw - la);
                float ld2 = fabsf(li_raw - lb);
                bool cond = (ld1 >= ld2);
                float dp = cond ? s2 : s1;
                float dn = cond ? s1 : s2;
                float near_l = cond ? lb : la;
                float far_l  = cond ? la : lb;
                float li = (li_raw - mu) / sigma;
                float nl = (near_l - mu) / sigma;
                float fl = (far_l  - mu) / sigma;
                float alpha = (li - fl) * (li - fl) - (li - nl) * (li - nl);
                float l = dp - dn + 0.5f * alpha;
                loss = l > 0.f ? l : 0.f;
            }
        }
        if (lane == 0) wl[wid] = loss;
        __syncthreads();
        if (tid == 0) {
            #pragma unroll
            for (int w = 0; w < 8; w++) cta_loss += wl[w];
        }
    }

    // ---- epilogue: publish partial, last CTA reduces (fixed order) ----
    if (tid == 0) {
        __stcg(&g_block[blockIdx.x], cta_loss);
        unsigned int old;
        asm volatile("atom.acq_rel.gpu.global.add.u32 %0, [%1], %2;"
                     : "=r"(old) : "l"(&g_count), "r"(1u) : "memory");
        isLast = (old == (unsigned int)gridDim.x - 1u);
    }
    __syncthreads();

    if (isLast) {
        const int nb = gridDim.x;
        float s = 0.f;
        for (int j = tid; j < nb; j += 256)
            s += __ldcg(&g_block[j]);
        s = warp_sum(s);
        if (lane == 0) sh1[wid] = s;
        __syncthreads();
        if (tid == 0) {
            float t = 0.f;
            #pragma unroll
            for (int w = 0; w < 8; w++) t += sh1[w];
            out[0] = t;
            g_count = 0;  // reset for next graph replay
        }
    }
}

extern "C" void kernel_launch(void* const* d_in, const int* in_sizes, int n_in,
                              void* d_out, int out_size) {
    const float* feats = (const float*)d_in[0];
    const float* label = (const float*)d_in[1];
    const int*   idx1  = (const int*)d_in[2];
    const int*   idx2  = (const int*)d_in[3];

    const int B = in_sizes[1];
    const int D = in_sizes[0] / B;
    const int nblocks = (B + 7) / 8;

    triplet_fused<<<nblocks, 256>>>(feats, label, idx1, idx2, (float*)d_out, B, D);
}